// round 17
// baseline (speedup 1.0000x reference)
#include <cuda_runtime.h>
#include <cuda_fp16.h>
#include <math.h>
#include <stdint.h>

#define BB   2
#define SS   2048
#define DIN  2048
#define NH   16
#define NKV  4
#define HD   128
#define GRP  4          // NH / NKV
#define SCALING 0.0625f // 256^-0.5
#define EPS  1e-6f

// ---------------- scratch (allocation-free: __device__ globals) ----------------
__device__ float g_q  [BB*SS*NH *HD];   // fp32 GEMM outputs (pre-norm)
__device__ float g_k  [BB*SS*NKV*HD];
__device__ float g_v  [BB*SS*NKV*HD];
__device__ __half g_qh [BB*SS*NH *HD];  // fp16 normed q (b,s,h,d)
__device__ __half g_kh [BB*SS*NKV*HD];  // fp16 normed k
__device__ __half g_vt [BB*NKV*HD*SS];  // fp16 v TRANSPOSED [(b*NKV+kv)*HD+d][s]
__device__ __half g_xh [BB*SS*DIN];     // x fp16 [M][K]
__device__ __half g_ch [BB*SS*NH*HD];   // ctx fp16 [M][K] (written by attention)
__device__ __half g_wqT[DIN*NH*HD];     // [N][K] fp16 transposed weights
__device__ __half g_wkT[DIN*NKV*HD];
__device__ __half g_wvT[DIN*NKV*HD];
__device__ __half g_woT[DIN*NH*HD];

// ================= mma / helpers =================
__device__ __forceinline__ uint32_t smem_u32(const void* p) {
    uint32_t a;
    asm("{ .reg .u64 t; cvta.to.shared.u64 t, %1; cvt.u32.u64 %0, t; }" : "=r"(a) : "l"(p));
    return a;
}
#define MMA_F16(C0,C1,C2,C3, A0,A1,A2,A3, B0,B1)                               \
    asm volatile("mma.sync.aligned.m16n8k16.row.col.f32.f16.f16.f32 "          \
                 "{%0,%1,%2,%3},{%4,%5,%6,%7},{%8,%9},{%0,%1,%2,%3};"          \
                 : "+f"(C0), "+f"(C1), "+f"(C2), "+f"(C3)                      \
                 : "r"(A0), "r"(A1), "r"(A2), "r"(A3), "r"(B0), "r"(B1))
#define LDSM_X4(R0,R1,R2,R3, ADDR)                                             \
    asm volatile("ldmatrix.sync.aligned.m8n8.x4.shared.b16 {%0,%1,%2,%3}, [%4];" \
        : "=r"(R0), "=r"(R1), "=r"(R2), "=r"(R3) : "r"(ADDR))

// ================= preprocessing =================
__global__ __launch_bounds__(256)
void transpose_f16(const float* __restrict__ W, __half* __restrict__ T, int K, int N)
{
    __shared__ float t[32][33];
    const int tx = threadIdx.x & 31, ty = threadIdx.x >> 5;
    const int kb = blockIdx.y * 32, nb = blockIdx.x * 32;
    #pragma unroll
    for (int i = 0; i < 4; i++)
        t[ty + i * 8][tx] = W[(size_t)(kb + ty + i * 8) * N + nb + tx];
    __syncthreads();
    #pragma unroll
    for (int i = 0; i < 4; i++)
        T[(size_t)(nb + ty + i * 8) * K + kb + tx] = __float2half(t[tx][ty + i * 8]);
}

// v fp32 [b][s][kv][d] -> vt fp16 [(b*NKV+kv)*HD + d][SS]
__global__ __launch_bounds__(256)
void transpose_v_f16(const float* __restrict__ v, __half* __restrict__ vt)
{
    __shared__ float t[32][33];
    const int tx = threadIdx.x & 31, ty = threadIdx.x >> 5;
    const int bkv = blockIdx.z;              // b*NKV + kv
    const int b = bkv / NKV, kv = bkv % NKV;
    const int s0 = blockIdx.x * 32, d0 = blockIdx.y * 32;
    #pragma unroll
    for (int i = 0; i < 4; i++)
        t[ty + i * 8][tx] = v[(((size_t)b * SS + s0 + ty + i * 8) * NKV + kv) * HD + d0 + tx];
    __syncthreads();
    #pragma unroll
    for (int i = 0; i < 4; i++)
        vt[((size_t)bkv * HD + d0 + ty + i * 8) * SS + s0 + tx] =
            __float2half(t[tx][ty + i * 8]);
}

__global__ __launch_bounds__(256)
void convert_f16(const float* __restrict__ X, __half* __restrict__ H, int n)
{
    int i = (blockIdx.x * 256 + threadIdx.x) * 8;
    if (i < n) {
        float4 a = *(const float4*)&X[i];
        float4 b = *(const float4*)&X[i + 4];
        __half2 h0 = __floats2half2_rn(a.x, a.y);
        __half2 h1 = __floats2half2_rn(a.z, a.w);
        __half2 h2 = __floats2half2_rn(b.x, b.y);
        __half2 h3 = __floats2half2_rn(b.z, b.w);
        *(uint4*)&H[i] = make_uint4(*(uint32_t*)&h0, *(uint32_t*)&h1,
                                    *(uint32_t*)&h2, *(uint32_t*)&h3);
    }
}

// ================= fp16 GEMM (R15 verbatim, proven) =================
#define GW 36
#define GTILE (128 * GW)
#define GEMM_SMEM_BYTES (4 * GTILE * 4)    // 73728 B

__global__ __launch_bounds__(256)
void gemm_f16s(const __half* __restrict__ A, const __half* __restrict__ B,
               float* __restrict__ C, int M, int N, int K)
{
    extern __shared__ uint32_t sg[];
    const uint32_t sbase = smem_u32(sg);
    const int tid  = threadIdx.x;
    const int lane = tid & 31;
    const int warp = tid >> 5;
    const int wm   = (warp >> 2) * 64;
    const int wn   = (warp & 3) * 32;
    const int m0   = blockIdx.y * 128;
    const int n0   = blockIdx.x * 128;
    const int lq   = lane >> 2, lr = lane & 3;

    const int srow = tid >> 1;
    const int sh   = (tid & 1) * 32;
    const __half* Ap = A + (size_t)(m0 + srow) * K + sh;
    const __half* Bp = B + (size_t)(n0 + srow) * K + sh;
    const uint32_t wst = srow * GW + (tid & 1) * 16;

    const uint32_t a_lane = (((lane & 15) + wm) * GW + (lane >> 4) * 4) * 4;
    const uint32_t b_lane = (((lane & 7) + wn + (lane >> 4) * 8) * GW
                             + ((lane >> 3) & 1) * 4) * 4;

    float c[4][4][4];
    #pragma unroll
    for (int mt = 0; mt < 4; mt++)
        #pragma unroll
        for (int nt = 0; nt < 4; nt++)
            #pragma unroll
            for (int e = 0; e < 4; e++) c[mt][nt][e] = 0.f;

    const int KT = K >> 6;

    #pragma unroll
    for (int i = 0; i < 4; i++) {
        *(uint4*)&sg[0 * GTILE + wst + i * 4] = *(const uint4*)(Ap + i * 8);
        *(uint4*)&sg[1 * GTILE + wst + i * 4] = *(const uint4*)(Bp + i * 8);
    }
    __syncthreads();

    int buf = 0;
    for (int kt = 0; kt < KT; kt++) {
        uint4 ra[4], rb[4];
        const bool has_next = (kt + 1 < KT);
        if (has_next) {
            const __half* ap = Ap + (size_t)(kt + 1) * 64;
            const __half* bp = Bp + (size_t)(kt + 1) * 64;
            #pragma unroll
            for (int i = 0; i < 4; i++) {
                ra[i] = *(const uint4*)(ap + i * 8);
                rb[i] = *(const uint4*)(bp + i * 8);
            }
        }

        const uint32_t abase = sbase + (uint32_t)(buf * 2 * GTILE) * 4;
        const uint32_t bbase = abase + (uint32_t)GTILE * 4;
        #pragma unroll
        for (int ks = 0; ks < 4; ks++) {
            const uint32_t koff = (uint32_t)(ks * 8) * 4;
            uint32_t af[4][4], bf[2][4];
            #pragma unroll
            for (int mt = 0; mt < 4; mt++)
                LDSM_X4(af[mt][0], af[mt][1], af[mt][2], af[mt][3],
                        abase + (uint32_t)(mt * 16 * GW) * 4 + koff + a_lane);
            #pragma unroll
            for (int t = 0; t < 2; t++)
                LDSM_X4(bf[t][0], bf[t][1], bf[t][2], bf[t][3],
                        bbase + (uint32_t)(t * 16 * GW) * 4 + koff + b_lane);
            #pragma unroll
            for (int mt = 0; mt < 4; mt++)
                #pragma unroll
                for (int nt = 0; nt < 4; nt++)
                    MMA_F16(c[mt][nt][0], c[mt][nt][1], c[mt][nt][2], c[mt][nt][3],
                            af[mt][0], af[mt][1], af[mt][2], af[mt][3],
                            bf[nt >> 1][(nt & 1) * 2], bf[nt >> 1][(nt & 1) * 2 + 1]);
        }

        if (has_next) {
            uint32_t* dst = sg + (buf ^ 1) * 2 * GTILE;
            #pragma unroll
            for (int i = 0; i < 4; i++) {
                *(uint4*)&dst[wst + i * 4]         = ra[i];
                *(uint4*)&dst[GTILE + wst + i * 4] = rb[i];
            }
            __syncthreads();
            buf ^= 1;
        }
    }

    #pragma unroll
    for (int mt = 0; mt < 4; mt++) {
        #pragma unroll
        for (int nt = 0; nt < 4; nt++) {
            int r  = m0 + wm + mt * 16 + lq;
            int cc = n0 + wn + nt * 8 + 2 * lr;
            *(float2*)&C[(size_t)r * N + cc]       = make_float2(c[mt][nt][0], c[mt][nt][1]);
            *(float2*)&C[(size_t)(r + 8) * N + cc] = make_float2(c[mt][nt][2], c[mt][nt][3]);
        }
    }
}

// ---------------- RMSNorm + RoPE: fp32 in, fp16 out ----------------
__global__ __launch_bounds__(128)
void norm_rope_f16o(const float* __restrict__ data, __half* __restrict__ outp,
                    const float* __restrict__ cosb, const float* __restrict__ sinb,
                    const float* __restrict__ scale, int heads, float extra_scale)
{
    const int r = blockIdx.x;
    const int s = (r / heads) % SS;
    const int d = threadIdx.x;
    const float* row = data + (size_t)r * HD;

    float val = row[d];
    float sq = val * val;
    #pragma unroll
    for (int off = 16; off; off >>= 1)
        sq += __shfl_xor_sync(0xffffffffu, sq, off);

    __shared__ float red[4];
    if ((d & 31) == 0) red[d >> 5] = sq;
    __syncthreads();
    float ss = red[0] + red[1] + red[2] + red[3];
    float rinv = rsqrtf(ss * (1.0f / HD) + EPS);
    float nrm = val * rinv * scale[d];

    __shared__ float buf[HD];
    buf[d] = nrm;
    __syncthreads();
    float partner = (d < HD / 2) ? -buf[d + HD / 2] : buf[d - HD / 2];
    float out = nrm * cosb[(size_t)s * HD + d] + partner * sinb[(size_t)s * HD + d];
    outp[(size_t)r * HD + d] = __float2half(out * extra_scale);
}

// ================= causal flash attention =================
// Layouts and ldmatrix maps identical to the proven R16 kernel. Changes:
//  - Q/K staged from pre-converted fp16 (pure uint4 copies)
//  - Vt staged from gmem-transposed fp16 v (pure uint4 copies)
//  - qb reversed so longest causal CTAs launch first
#define QH_STR 68
#define VT_STR 36
#define PS_STR 36
#define QS_OFF 0
#define KS_OFF (64 * QH_STR)            // 4352
#define VT_OFF (KS_OFF + 64 * QH_STR)   // 8704
#define PS_OFF (VT_OFF + 128 * VT_STR)  // 13312
#define ATT_SMEM_U32 (PS_OFF + 64 * PS_STR)    // 15616
#define ATT_SMEM_BYTES (ATT_SMEM_U32 * 4)      // 62464

__global__ __launch_bounds__(128)
void attn_hyb(const __half* __restrict__ qh, const __half* __restrict__ kh,
              const __half* __restrict__ vt, __half* __restrict__ ctx)
{
    extern __shared__ uint32_t sm[];
    uint32_t* Qs = sm + QS_OFF;
    uint32_t* Ks = sm + KS_OFF;
    uint32_t* Vt = sm + VT_OFF;
    uint32_t* Ps = sm + PS_OFF;
    const uint32_t sbase  = smem_u32(sm);
    const uint32_t qbase  = sbase + QS_OFF * 4;
    const uint32_t kbase  = sbase + KS_OFF * 4;
    const uint32_t vtbase = sbase + VT_OFF * 4;
    const uint32_t psbase = sbase + PS_OFF * 4;

    const int qb = (int)gridDim.x - 1 - (int)blockIdx.x;   // longest first
    const int h = blockIdx.y, b = blockIdx.z;
    const int kvh = h / GRP;
    const int q0 = qb * 64;
    const int tid = threadIdx.x;
    const int lane = tid & 31;
    const int warp = tid >> 5;       // 0..3
    const int wm = warp * 16;
    const int lq = lane >> 2;
    const int lr = lane & 3;

    const uint32_t aq_lane = (((lane & 15) + wm) * QH_STR + (lane >> 4) * 4) * 4;
    const uint32_t bk_lane = (((lane & 7) + (lane >> 4) * 8) * QH_STR
                              + ((lane >> 3) & 1) * 4) * 4;
    const uint32_t ap_lane = (((lane & 15) + wm) * PS_STR + (lane >> 4) * 4) * 4;
    const uint32_t bv_lane = (((lane & 7) + (lane >> 4) * 8) * VT_STR
                              + ((lane >> 3) & 1) * 4) * 4;

    // Q tile: pure uint4 copies (row = 16 uint4 of 8 halves)
    for (int idx = tid; idx < 64 * 16; idx += 128) {
        int i = idx >> 4, w = idx & 15;
        uint4 vq = *(const uint4*)(qh + ((((size_t)b * SS + q0 + i) * NH) + h) * HD + w * 8);
        *(uint4*)&Qs[i * QH_STR + w * 4] = vq;
    }

    float o[16][4];
    #pragma unroll
    for (int nt = 0; nt < 16; nt++)
        #pragma unroll
        for (int e = 0; e < 4; e++) o[nt][e] = 0.f;
    float mrow[2] = {-1e30f, -1e30f};
    float lrow[2] = {0.f, 0.f};

    const size_t vt_head = ((size_t)b * NKV + kvh) * HD;

    for (int kb = 0; kb <= qb; kb++) {
        const int k0 = kb * 64;
        __syncthreads();

        // K: 64 rows x 16 uint4
        for (int idx = tid; idx < 64 * 16; idx += 128) {
            int j = idx >> 4, w = idx & 15;
            uint4 vk = *(const uint4*)(kh + (((size_t)b * SS + k0 + j) * NKV + kvh) * HD + w * 8);
            *(uint4*)&Ks[j * QH_STR + w * 4] = vk;
        }
        // Vt: 128 rows x 8 uint4 (64 halves of the s-window)
        for (int idx = tid; idx < 128 * 8; idx += 128) {
            int d = idx >> 3, w = idx & 7;
            uint4 vv = *(const uint4*)(vt + (vt_head + d) * SS + k0 + w * 8);
            *(uint4*)&Vt[d * VT_STR + w * 4] = vv;
        }
        __syncthreads();

        const bool active = (k0 <= q0 + wm + 15);
        if (active) {
            // ---- S = Q K^T (fp16, ldmatrix) ----
            float s[8][4];
            #pragma unroll
            for (int nt = 0; nt < 8; nt++)
                #pragma unroll
                for (int e = 0; e < 4; e++) s[nt][e] = 0.f;

            #pragma unroll
            for (int ks = 0; ks < 8; ks++) {
                const uint32_t koff = (uint32_t)(ks * 8) * 4;
                uint32_t af[4], bf[4][4];
                LDSM_X4(af[0], af[1], af[2], af[3], qbase + koff + aq_lane);
                #pragma unroll
                for (int t = 0; t < 4; t++)
                    LDSM_X4(bf[t][0], bf[t][1], bf[t][2], bf[t][3],
                            kbase + (uint32_t)(t * 16 * QH_STR) * 4 + koff + bk_lane);
                #pragma unroll
                for (int nt = 0; nt < 8; nt++)
                    MMA_F16(s[nt][0], s[nt][1], s[nt][2], s[nt][3],
                            af[0], af[1], af[2], af[3],
                            bf[nt >> 1][(nt & 1) * 2], bf[nt >> 1][(nt & 1) * 2 + 1]);
            }

            // causal mask on the diagonal tile
            if (kb == qb) {
                int i0 = q0 + wm + lq;
                #pragma unroll
                for (int nt = 0; nt < 8; nt++) {
                    int j0 = k0 + nt * 8 + 2 * lr;
                    if (j0     > i0)     s[nt][0] = -1e30f;
                    if (j0 + 1 > i0)     s[nt][1] = -1e30f;
                    if (j0     > i0 + 8) s[nt][2] = -1e30f;
                    if (j0 + 1 > i0 + 8) s[nt][3] = -1e30f;
                }
            }

            // ---- online softmax (proven) ----
            #pragma unroll
            for (int hh = 0; hh < 2; hh++) {
                float rmax = -1e30f;
                #pragma unroll
                for (int nt = 0; nt < 8; nt++)
                    rmax = fmaxf(rmax, fmaxf(s[nt][2 * hh], s[nt][2 * hh + 1]));
                rmax = fmaxf(rmax, __shfl_xor_sync(0xffffffffu, rmax, 1));
                rmax = fmaxf(rmax, __shfl_xor_sync(0xffffffffu, rmax, 2));

                float mnew  = fmaxf(mrow[hh], rmax);
                float alpha = __expf(mrow[hh] - mnew);
                mrow[hh] = mnew;

                float rsum = 0.f;
                int prow = (wm + lq + 8 * hh) * PS_STR;
                #pragma unroll
                for (int nt = 0; nt < 8; nt++) {
                    float p0 = __expf(s[nt][2 * hh]     - mnew);
                    float p1 = __expf(s[nt][2 * hh + 1] - mnew);
                    rsum += p0 + p1;
                    __half2 hp = __floats2half2_rn(p0, p1);
                    Ps[prow + nt * 4 + lr] = *(uint32_t*)&hp;
                }
                rsum += __shfl_xor_sync(0xffffffffu, rsum, 1);
                rsum += __shfl_xor_sync(0xffffffffu, rsum, 2);
                lrow[hh] = lrow[hh] * alpha + rsum;

                #pragma unroll
                for (int nt = 0; nt < 16; nt++) {
                    o[nt][2 * hh]     *= alpha;
                    o[nt][2 * hh + 1] *= alpha;
                }
            }
            __syncwarp();

            // ---- O += P V (fp16, ldmatrix) ----
            #pragma unroll
            for (int ks = 0; ks < 4; ks++) {
                const uint32_t koff = (uint32_t)(ks * 8) * 4;
                uint32_t af[4], bf[8][4];
                LDSM_X4(af[0], af[1], af[2], af[3], psbase + koff + ap_lane);
                #pragma unroll
                for (int t = 0; t < 8; t++)
                    LDSM_X4(bf[t][0], bf[t][1], bf[t][2], bf[t][3],
                            vtbase + (uint32_t)(t * 16 * VT_STR) * 4 + koff + bv_lane);
                #pragma unroll
                for (int nt = 0; nt < 16; nt++)
                    MMA_F16(o[nt][0], o[nt][1], o[nt][2], o[nt][3],
                            af[0], af[1], af[2], af[3],
                            bf[nt >> 1][(nt & 1) * 2], bf[nt >> 1][(nt & 1) * 2 + 1]);
            }
        }
    }

    // epilogue: divide by l, write ctx fp16 (b,s,h,d)
    #pragma unroll
    for (int hh = 0; hh < 2; hh++) {
        float inv = 1.0f / lrow[hh];
        int row = q0 + wm + lq + 8 * hh;
        size_t base = (((size_t)b * SS + row) * NH + h) * HD;
        #pragma unroll
        for (int nt = 0; nt < 16; nt++) {
            int d = nt * 8 + 2 * lr;
            __half2 vv = __floats2half2_rn(o[nt][2 * hh] * inv, o[nt][2 * hh + 1] * inv);
            *(__half2*)&ctx[base + d] = vv;
        }
    }
}

// ---------------- launch ----------------
extern "C" void kernel_launch(void* const* d_in, const int* in_sizes, int n_in,
                              void* d_out, int out_size)
{
    const float* x       = (const float*)d_in[0];
    const float* cosb    = (const float*)d_in[2];
    const float* sinb    = (const float*)d_in[3];
    const float* Wq      = (const float*)d_in[4];
    const float* Wk      = (const float*)d_in[5];
    const float* Wv      = (const float*)d_in[6];
    const float* Wo      = (const float*)d_in[7];
    const float* q_scale = (const float*)d_in[8];
    const float* k_scale = (const float*)d_in[9];
    float* out = (float*)d_out;

    float *q, *k, *v;
    cudaGetSymbolAddress((void**)&q, g_q);
    cudaGetSymbolAddress((void**)&k, g_k);
    cudaGetSymbolAddress((void**)&v, g_v);
    __half *qh, *kh, *vt, *xh, *ch, *wqT, *wkT, *wvT, *woT;
    cudaGetSymbolAddress((void**)&qh,  g_qh);
    cudaGetSymbolAddress((void**)&kh,  g_kh);
    cudaGetSymbolAddress((void**)&vt,  g_vt);
    cudaGetSymbolAddress((void**)&xh,  g_xh);
    cudaGetSymbolAddress((void**)&ch,  g_ch);
    cudaGetSymbolAddress((void**)&wqT, g_wqT);
    cudaGetSymbolAddress((void**)&wkT, g_wkT);
    cudaGetSymbolAddress((void**)&wvT, g_wvT);
    cudaGetSymbolAddress((void**)&woT, g_woT);

    const int M = BB * SS;   // 4096

    // preprocessing
    transpose_f16<<<dim3((NH * HD) / 32, DIN / 32), 256>>>(Wq, wqT, DIN, NH * HD);
    transpose_f16<<<dim3((NKV * HD) / 32, DIN / 32), 256>>>(Wk, wkT, DIN, NKV * HD);
    transpose_f16<<<dim3((NKV * HD) / 32, DIN / 32), 256>>>(Wv, wvT, DIN, NKV * HD);
    transpose_f16<<<dim3(DIN / 32, (NH * HD) / 32), 256>>>(Wo, woT, NH * HD, DIN);
    convert_f16<<<M * DIN / 8 / 256, 256>>>(x, xh, M * DIN);

    // projections (fp16 mma + ldmatrix, fp32 out)
    cudaFuncSetAttribute(gemm_f16s, cudaFuncAttributeMaxDynamicSharedMemorySize,
                         GEMM_SMEM_BYTES);
    gemm_f16s<<<dim3((NH * HD) / 128, M / 128), 256, GEMM_SMEM_BYTES>>>(
        xh, wqT, q, M, NH * HD, DIN);
    gemm_f16s<<<dim3((NKV * HD) / 128, M / 128), 256, GEMM_SMEM_BYTES>>>(
        xh, wkT, k, M, NKV * HD, DIN);
    gemm_f16s<<<dim3((NKV * HD) / 128, M / 128), 256, GEMM_SMEM_BYTES>>>(
        xh, wvT, v, M, NKV * HD, DIN);

    // rmsnorm + rope -> fp16; v -> fp16 transposed
    norm_rope_f16o<<<BB * SS * NH,  128>>>(q, qh, cosb, sinb, q_scale, NH,  SCALING);
    norm_rope_f16o<<<BB * SS * NKV, 128>>>(k, kh, cosb, sinb, k_scale, NKV, 1.0f);
    transpose_v_f16<<<dim3(SS / 32, HD / 32, BB * NKV), 256>>>(v, vt);

    // attention (all-fp16 MMA + ldmatrix, pure-copy staging)
    cudaFuncSetAttribute(attn_hyb, cudaFuncAttributeMaxDynamicSharedMemorySize,
                         ATT_SMEM_BYTES);
    attn_hyb<<<dim3(SS / 64, NH, BB), 128, ATT_SMEM_BYTES>>>(qh, kh, vt, ch);

    // output projection (fp16 ctx -> fp32 out)
    gemm_f16s<<<dim3(DIN / 128, M / 128), 256, GEMM_SMEM_BYTES>>>(
        ch, woT, out, M, DIN, DIN);
}